// round 1
// baseline (speedup 1.0000x reference)
#include <cuda_runtime.h>

// Problem shapes (fixed)
#define BSZ 16
#define TT  1024
#define EMB 768
#define HID 1024
#define MROWS (BSZ*TT)   // 16384 rows per tensor

// ---------------- scratch (device globals; no allocation allowed) ----------
__device__ float g_H [2ull * MROWS * HID];               // hidden layer (A then B halves)
__device__ float g_F [2ull * MROWS * HID];               // MLP outputs f_A, f_B
__device__ float g_E [(unsigned long long)BSZ * TT * TT]; // e, later overwritten by row-softmax P
__device__ float g_P2[(unsigned long long)BSZ * TT * TT]; // column-softmax, stored transposed (tb, ta)
__device__ float g_rmax[MROWS], g_rsum[MROWS];
__device__ float g_cmax[MROWS], g_csum[MROWS];

// ---------------- generic tiled SGEMM: C = act(A @ B(^T) + bias) -----------
// BM=BN=128, BK=8, 256 threads, 8x8 microtile. All dims divide evenly here.
template<bool TRANSB, bool BIASRELU>
__global__ void __launch_bounds__(256)
sgemm_kernel(const float* __restrict__ A, const float* __restrict__ B,
             const float* __restrict__ bias, float* __restrict__ C,
             int M, int N, int K,
             size_t sA, size_t sB, size_t sC)
{
    constexpr int BM = 128, BN = 128, BK = 8;
    __shared__ float As[BK][BM + 4];
    __shared__ float Bs[BK][BN + 4];

    const int bz = blockIdx.z;
    A += (size_t)bz * sA;
    B += (size_t)bz * sB;
    C += (size_t)bz * sC;

    const int m0 = blockIdx.y * BM;
    const int n0 = blockIdx.x * BN;
    const int tid = threadIdx.x;

    // A tile load: 128 rows x 8 k-cols, one float4 per thread, store transposed
    const int ar = tid >> 1;
    const int ac = (tid & 1) * 4;
    // B (K x N) NN load: 8 rows x 128 cols
    const int br = tid >> 5;
    const int bc = (tid & 31) * 4;

    const int tm = (tid >> 4) * 8;
    const int tn = (tid & 15) * 8;

    float acc[8][8];
#pragma unroll
    for (int i = 0; i < 8; ++i)
#pragma unroll
        for (int j = 0; j < 8; ++j) acc[i][j] = 0.f;

    for (int kb = 0; kb < K; kb += BK) {
        float4 av = *reinterpret_cast<const float4*>(A + (size_t)(m0 + ar) * K + kb + ac);
        As[ac + 0][ar] = av.x; As[ac + 1][ar] = av.y;
        As[ac + 2][ar] = av.z; As[ac + 3][ar] = av.w;

        if (TRANSB) {
            // B is (N x K) row-major
            float4 bv = *reinterpret_cast<const float4*>(B + (size_t)(n0 + ar) * K + kb + ac);
            Bs[ac + 0][ar] = bv.x; Bs[ac + 1][ar] = bv.y;
            Bs[ac + 2][ar] = bv.z; Bs[ac + 3][ar] = bv.w;
        } else {
            float4 bv = *reinterpret_cast<const float4*>(B + (size_t)(kb + br) * N + n0 + bc);
            *reinterpret_cast<float4*>(&Bs[br][bc]) = bv;
        }
        __syncthreads();

#pragma unroll
        for (int kk = 0; kk < BK; ++kk) {
            float4 a0 = *reinterpret_cast<const float4*>(&As[kk][tm]);
            float4 a1 = *reinterpret_cast<const float4*>(&As[kk][tm + 4]);
            float4 b0 = *reinterpret_cast<const float4*>(&Bs[kk][tn]);
            float4 b1 = *reinterpret_cast<const float4*>(&Bs[kk][tn + 4]);
            float aa[8] = {a0.x, a0.y, a0.z, a0.w, a1.x, a1.y, a1.z, a1.w};
            float bb[8] = {b0.x, b0.y, b0.z, b0.w, b1.x, b1.y, b1.z, b1.w};
#pragma unroll
            for (int i = 0; i < 8; ++i)
#pragma unroll
                for (int j = 0; j < 8; ++j)
                    acc[i][j] = fmaf(aa[i], bb[j], acc[i][j]);
        }
        __syncthreads();
    }

    float bv[8];
#pragma unroll
    for (int j = 0; j < 8; ++j) bv[j] = BIASRELU ? bias[n0 + tn + j] : 0.f;

#pragma unroll
    for (int i = 0; i < 8; ++i) {
        float out[8];
#pragma unroll
        for (int j = 0; j < 8; ++j) {
            float v = acc[i][j];
            if (BIASRELU) v = fmaxf(v + bv[j], 0.f);
            out[j] = v;
        }
        float* cp = C + (size_t)(m0 + tm + i) * N + n0 + tn;
        *reinterpret_cast<float4*>(cp)     = make_float4(out[0], out[1], out[2], out[3]);
        *reinterpret_cast<float4*>(cp + 4) = make_float4(out[4], out[5], out[6], out[7]);
    }
}

// ---------------- row softmax stats: one warp per row (length 1024) --------
__global__ void __launch_bounds__(256)
rowstats_kernel(const float* __restrict__ E, float* __restrict__ rmax, float* __restrict__ rsum)
{
    int r = blockIdx.x * 8 + (threadIdx.x >> 5);
    int lane = threadIdx.x & 31;
    const float* row = E + (size_t)r * TT;

    float v[32];
    float m = -1e30f;
#pragma unroll
    for (int i = 0; i < 8; ++i) {
        float4 t = *reinterpret_cast<const float4*>(row + i * 128 + lane * 4);
        v[i * 4 + 0] = t.x; v[i * 4 + 1] = t.y; v[i * 4 + 2] = t.z; v[i * 4 + 3] = t.w;
        m = fmaxf(m, fmaxf(fmaxf(t.x, t.y), fmaxf(t.z, t.w)));
    }
#pragma unroll
    for (int o = 16; o > 0; o >>= 1) m = fmaxf(m, __shfl_xor_sync(0xffffffffu, m, o));

    float s = 0.f;
#pragma unroll
    for (int i = 0; i < 32; ++i) s += __expf(v[i] - m);
#pragma unroll
    for (int o = 16; o > 0; o >>= 1) s += __shfl_xor_sync(0xffffffffu, s, o);

    if (lane == 0) { rmax[r] = m; rsum[r] = s; }
}

// ---------------- column softmax stats: one thread per column, 2 passes ----
__global__ void __launch_bounds__(256)
colstats_kernel(const float* __restrict__ E, float* __restrict__ cmax, float* __restrict__ csum)
{
    int b = blockIdx.x >> 2;
    int c = ((blockIdx.x & 3) << 8) + threadIdx.x;
    const float* base = E + (size_t)b * TT * TT + c;

    float m = -1e30f;
#pragma unroll 8
    for (int a = 0; a < TT; ++a) m = fmaxf(m, base[(size_t)a * TT]);

    float s = 0.f;
#pragma unroll 8
    for (int a = 0; a < TT; ++a) s += __expf(base[(size_t)a * TT] - m);

    cmax[b * TT + c] = m;
    csum[b * TT + c] = s;
}

// -------- normalize: P = row-softmax(e) in place; P2 = col-softmax, transposed
__global__ void __launch_bounds__(256)
normexp_kernel(float* __restrict__ E, float* __restrict__ P2,
               const float* __restrict__ rmax, const float* __restrict__ rsum,
               const float* __restrict__ cmax, const float* __restrict__ csum)
{
    __shared__ float tile[32][33];
    int b = blockIdx.z;
    int a0 = blockIdx.y * 32, c0 = blockIdx.x * 32;
    int tx = threadIdx.x, ty = threadIdx.y;

    float* Eb = E  + (size_t)b * TT * TT;
    float* Pb = P2 + (size_t)b * TT * TT;

#pragma unroll
    for (int k = 0; k < 4; ++k) {
        int a = a0 + k * 8 + ty;
        float v = Eb[(size_t)a * TT + c0 + tx];
        tile[k * 8 + ty][tx] = v;
        int gr = b * TT + a;
        Eb[(size_t)a * TT + c0 + tx] = __expf(v - rmax[gr]) * __frcp_rn(rsum[gr]);
    }
    __syncthreads();
#pragma unroll
    for (int k = 0; k < 4; ++k) {
        int c = c0 + k * 8 + ty;
        float v = tile[tx][k * 8 + ty];   // element (a0+tx, c)
        int gc = b * TT + c;
        Pb[(size_t)c * TT + a0 + tx] = __expf(v - cmax[gc]) * __frcp_rn(csum[gc]);
    }
}

// ---------------------------------------------------------------------------
extern "C" void kernel_launch(void* const* d_in, const int* in_sizes, int n_in,
                              void* d_out, int out_size)
{
    const float* Ain = (const float*)d_in[0];
    const float* Bin = (const float*)d_in[1];
    const float* W1  = (const float*)d_in[2];
    const float* b1  = (const float*)d_in[3];
    const float* W2  = (const float*)d_in[4];
    const float* b2  = (const float*)d_in[5];
    float* outp = (float*)d_out;

    float *H, *F, *E, *P2, *rm, *rs, *cm, *cs;
    cudaGetSymbolAddress((void**)&H,  g_H);
    cudaGetSymbolAddress((void**)&F,  g_F);
    cudaGetSymbolAddress((void**)&E,  g_E);
    cudaGetSymbolAddress((void**)&P2, g_P2);
    cudaGetSymbolAddress((void**)&rm, g_rmax);
    cudaGetSymbolAddress((void**)&rs, g_rsum);
    cudaGetSymbolAddress((void**)&cm, g_cmax);
    cudaGetSymbolAddress((void**)&cs, g_csum);

    // Layer 1: H = relu(X @ W1 + b1), X in {A, B}  (16384 x 768) @ (768 x 1024)
    sgemm_kernel<false, true><<<dim3(HID / 128, MROWS / 128, 1), 256>>>(
        Ain, W1, b1, H, MROWS, HID, EMB, 0, 0, 0);
    sgemm_kernel<false, true><<<dim3(HID / 128, MROWS / 128, 1), 256>>>(
        Bin, W1, b1, H + (size_t)MROWS * HID, MROWS, HID, EMB, 0, 0, 0);

    // Layer 2: F = relu(H @ W2 + b2)  (32768 x 1024) @ (1024 x 1024)
    sgemm_kernel<false, true><<<dim3(HID / 128, (2 * MROWS) / 128, 1), 256>>>(
        H, W2, b2, F, 2 * MROWS, HID, HID, 0, 0, 0);

    // e[b] = f_A[b] @ f_B[b]^T   (1024 x 1024 x 1024) x 16 batches
    sgemm_kernel<true, false><<<dim3(TT / 128, TT / 128, BSZ), 256>>>(
        F, F + (size_t)MROWS * HID, nullptr, E, TT, TT, HID,
        (size_t)TT * HID, (size_t)TT * HID, (size_t)TT * TT);

    // softmax stats
    rowstats_kernel<<<MROWS / 8, 256>>>(E, rm, rs);
    colstats_kernel<<<BSZ * 4, 256>>>(E, cm, cs);

    // normalize: E <- row-softmax(e), P2 <- col-softmax(e) transposed (tb, ta)
    normexp_kernel<<<dim3(TT / 32, TT / 32, BSZ), dim3(32, 8)>>>(E, P2, rm, rs, cm, cs);

    // beta[b] = P[b] @ B[b]   (1024 x 1024) @ (1024 x 768)
    sgemm_kernel<false, false><<<dim3(EMB / 128, TT / 128, BSZ), 256>>>(
        E, Bin, nullptr, outp, TT, EMB, TT,
        (size_t)TT * TT, (size_t)TT * EMB, (size_t)TT * EMB);

    // alpha[b] = P2[b] @ A[b]  (1024 x 1024) @ (1024 x 768)
    sgemm_kernel<false, false><<<dim3(EMB / 128, TT / 128, BSZ), 256>>>(
        P2, Ain, nullptr, outp + (size_t)BSZ * TT * EMB, TT, EMB, TT,
        (size_t)TT * TT, (size_t)TT * EMB, (size_t)TT * EMB);
}

// round 3
// speedup vs baseline: 1.4012x; 1.4012x over previous
#include <cuda_runtime.h>
#include <cstdint>

// Problem shapes (fixed)
#define BSZ 16
#define TT  1024
#define EMB 768
#define HID 1024
#define MROWS (BSZ*TT)   // 16384 rows per tensor

// ======================= scratch (device globals) ==========================
// ABs: split(A) rows then split(B) rows: (2*MROWS) x (2*EMB) = [hi|lo] along K
__device__ __align__(128) float g_ABs [(size_t)2 * MROWS * 2 * EMB];
__device__ __align__(128) float g_W1Ts[(size_t)HID * 2 * EMB];        // W1^T split (1024 x 1536)
__device__ __align__(128) float g_W2Ts[(size_t)HID * 2 * HID];        // W2^T split (1024 x 2048)
__device__ __align__(128) float g_Hs  [(size_t)2 * MROWS * 2 * HID];  // hidden split (32768 x 2048)
__device__ __align__(128) float g_Fs  [(size_t)2 * MROWS * 2 * HID];  // MLP out split (32768 x 2048)
__device__ __align__(128) float g_E   [(size_t)BSZ * TT * TT];        // e -> row softmax P (in place)
__device__ __align__(128) float g_P2  [(size_t)BSZ * TT * TT];        // col softmax, transposed (tb, ta)
__device__ __align__(128) float g_AT  [(size_t)BSZ * EMB * TT];       // Ain^T per batch (768 x 1024), tf32
__device__ __align__(128) float g_BT  [(size_t)BSZ * EMB * TT];       // Bin^T per batch, tf32
__device__ float g_rmax[MROWS], g_rsum[MROWS];
__device__ float g_cmax[MROWS], g_csum[MROWS];

// ======================= helpers ===========================================
__device__ __forceinline__ uint32_t smem_u32(const void* p) {
    uint32_t a;
    asm("{ .reg .u64 t; cvta.to.shared.u64 t, %1; cvt.u32.u64 %0, t; }" : "=r"(a) : "l"(p));
    return a;
}
__device__ __forceinline__ float to_tf32(float x) {
    uint32_t u;
    asm("cvt.rna.tf32.f32 %0, %1;" : "=r"(u) : "f"(x));
    return __uint_as_float(u);
}
__device__ __forceinline__ void mma_tf32(float* d, const uint32_t* a, const uint32_t* b) {
    asm volatile(
        "mma.sync.aligned.m16n8k8.row.col.f32.tf32.tf32.f32 "
        "{%0,%1,%2,%3}, {%4,%5,%6,%7}, {%8,%9}, {%0,%1,%2,%3};"
        : "+f"(d[0]), "+f"(d[1]), "+f"(d[2]), "+f"(d[3])
        : "r"(a[0]), "r"(a[1]), "r"(a[2]), "r"(a[3]), "r"(b[0]), "r"(b[1]));
}

// ======================= tf32 mma.sync GEMM ================================
// C(M,N) = [act](sum over phases A_ph(M,K) * B_ph(N,K)^T + bias)
// A, B both K-major. BM=256, BN=128, BK=32. 8 warps = 4(m) x 2(n), 64x64/warp.
#define BM 256
#define BN 128
#define BK 32
#define SSTRIDE 36                       // padded floats per row (conflict-free)
#define STAGE_FLOATS ((BM + BN) * SSTRIDE)
#define STAGE_A_FLOATS (BM * SSTRIDE)
#define NSTAGE 3
#define GEMM_SMEM (NSTAGE * STAGE_FLOATS * 4)

__device__ __forceinline__ void cp_stage(float* smA, float* smB,
                                         const float* ga, int lda,
                                         const float* gb, int ldb, int tid)
{
    uint32_t a32 = smem_u32(smA);
    uint32_t b32 = smem_u32(smB);
#pragma unroll
    for (int i = 0; i < 8; ++i) {                 // 256 rows x 8 chunks
        int u = tid + i * 256;
        int r = u >> 3, c = (u & 7) * 4;
        asm volatile("cp.async.cg.shared.global [%0], [%1], 16;"
            :: "r"(a32 + (uint32_t)(r * SSTRIDE + c) * 4),
               "l"(ga + (size_t)r * lda + c) : "memory");
    }
#pragma unroll
    for (int i = 0; i < 4; ++i) {                 // 128 rows x 8 chunks
        int u = tid + i * 256;
        int r = u >> 3, c = (u & 7) * 4;
        asm volatile("cp.async.cg.shared.global [%0], [%1], 16;"
            :: "r"(b32 + (uint32_t)(r * SSTRIDE + c) * 4),
               "l"(gb + (size_t)r * ldb + c) : "memory");
    }
}

template<int NPHASE, bool BIASRELU, bool SPLITOUT>
__global__ void __launch_bounds__(256, 1)
gemm_mma(const float* __restrict__ Aop, int lda, unsigned long long sA,
         const float* __restrict__ Bop, int ldb, unsigned long long sB,
         const float* __restrict__ bias,
         float* __restrict__ C, int ldc, unsigned long long sC,
         int N, int K,
         int offA1, int offA2, int offB1, int offB2)
{
    extern __shared__ __align__(128) float sm[];
    const int tid  = threadIdx.x;
    const int lane = tid & 31;
    const int wid  = tid >> 5;
    const int wm   = wid >> 1;        // 0..3
    const int wn   = wid & 1;         // 0..1
    const int m0 = blockIdx.y * BM;
    const int n0 = blockIdx.x * BN;
    Aop += (size_t)blockIdx.z * sA;
    Bop += (size_t)blockIdx.z * sB;
    C   += (size_t)blockIdx.z * sC;

    const int KB = K / BK;
    const int NT = NPHASE * KB;
    const float* Abase = Aop + (size_t)m0 * lda;
    const float* Bbase = Bop + (size_t)n0 * ldb;

    float acc[4][8][4];
#pragma unroll
    for (int i = 0; i < 4; ++i)
#pragma unroll
        for (int j = 0; j < 8; ++j)
#pragma unroll
            for (int k = 0; k < 4; ++k) acc[i][j][k] = 0.f;

    // ---- prologue: stages 0,1 -----------------------------------------
#pragma unroll 1
    for (int s = 0; s < 2; ++s) {
        int ph = s / KB;                 // handles KB==1 edge (not hit here)
        int kk = s - ph * KB;
        int oa = (ph == 1) ? offA1 : ((ph == 2) ? offA2 : 0);
        int ob = (ph == 1) ? offB1 : ((ph == 2) ? offB2 : 0);
        float* st = sm + s * STAGE_FLOATS;
        cp_stage(st, st + STAGE_A_FLOATS, Abase + oa + kk * BK, lda,
                 Bbase + ob + kk * BK, ldb, tid);
        asm volatile("cp.async.commit_group;" ::: "memory");
    }

    const int a_r = lane >> 2;    // 0..7
    const int a_c = lane & 3;     // 0..3

#pragma unroll 1
    for (int kt = 0; kt < NT; ++kt) {
        asm volatile("cp.async.wait_group 1;" ::: "memory");
        __syncthreads();

        // prefetch kt+2
        {
            int nt = kt + 2;
            if (nt < NT) {
                int ph = nt / KB;
                int kk = nt - ph * KB;
                int oa = (ph == 1) ? offA1 : ((ph == 2) ? offA2 : 0);
                int ob = (ph == 1) ? offB1 : ((ph == 2) ? offB2 : 0);
                float* st = sm + (nt % NSTAGE) * STAGE_FLOATS;
                cp_stage(st, st + STAGE_A_FLOATS, Abase + oa + kk * BK, lda,
                         Bbase + ob + kk * BK, ldb, tid);
            }
            asm volatile("cp.async.commit_group;" ::: "memory");
        }

        // compute on stage kt%3
        const float* sA = sm + (kt % NSTAGE) * STAGE_FLOATS;
        const float* sB = sA + STAGE_A_FLOATS;
#pragma unroll
        for (int ks = 0; ks < 4; ++ks) {
            uint32_t af[4][4];
            uint32_t bf[8][2];
#pragma unroll
            for (int mi = 0; mi < 4; ++mi) {
                int r0 = wm * 64 + mi * 16 + a_r;
                int c0 = ks * 8 + a_c;
                af[mi][0] = __float_as_uint(sA[r0 * SSTRIDE + c0]);
                af[mi][1] = __float_as_uint(sA[(r0 + 8) * SSTRIDE + c0]);
                af[mi][2] = __float_as_uint(sA[r0 * SSTRIDE + c0 + 4]);
                af[mi][3] = __float_as_uint(sA[(r0 + 8) * SSTRIDE + c0 + 4]);
            }
#pragma unroll
            for (int ni = 0; ni < 8; ++ni) {
                int n = wn * 64 + ni * 8 + a_r;
                int k0 = ks * 8 + a_c;
                bf[ni][0] = __float_as_uint(sB[n * SSTRIDE + k0]);
                bf[ni][1] = __float_as_uint(sB[n * SSTRIDE + k0 + 4]);
            }
#pragma unroll
            for (int mi = 0; mi < 4; ++mi)
#pragma unroll
                for (int ni = 0; ni < 8; ++ni)
                    mma_tf32(acc[mi][ni], af[mi], bf[ni]);
        }
    }

    // ---- epilogue ------------------------------------------------------
#pragma unroll
    for (int ni = 0; ni < 8; ++ni) {
        int col = n0 + wn * 64 + ni * 8 + 2 * a_c;
        float b0 = 0.f, b1 = 0.f;
        if (BIASRELU) { b0 = __ldg(bias + col); b1 = __ldg(bias + col + 1); }
#pragma unroll
        for (int mi = 0; mi < 4; ++mi) {
            int row0 = m0 + wm * 64 + mi * 16 + a_r;
            float v00 = acc[mi][ni][0], v01 = acc[mi][ni][1];
            float v10 = acc[mi][ni][2], v11 = acc[mi][ni][3];
            if (BIASRELU) {
                v00 = fmaxf(v00 + b0, 0.f); v01 = fmaxf(v01 + b1, 0.f);
                v10 = fmaxf(v10 + b0, 0.f); v11 = fmaxf(v11 + b1, 0.f);
            }
            if (SPLITOUT) {
                float h00 = to_tf32(v00), h01 = to_tf32(v01);
                float h10 = to_tf32(v10), h11 = to_tf32(v11);
                float* p0 = C + (size_t)row0 * ldc + col;
                float* p1 = C + (size_t)(row0 + 8) * ldc + col;
                *(float2*)p0       = make_float2(h00, h01);
                *(float2*)(p0 + N) = make_float2(v00 - h00, v01 - h01);
                *(float2*)p1       = make_float2(h10, h11);
                *(float2*)(p1 + N) = make_float2(v10 - h10, v11 - h11);
            } else {
                *(float2*)(C + (size_t)row0 * ldc + col)       = make_float2(v00, v01);
                *(float2*)(C + (size_t)(row0 + 8) * ldc + col) = make_float2(v10, v11);
            }
        }
    }
}

// ======================= aux kernels =======================================
// split X (rows x C) -> Xs (rows x 2C): [hi | lo] along columns
__global__ void __launch_bounds__(256)
split_kernel(const float4* __restrict__ X, float4* __restrict__ Xs, int C4)
{
    size_t i = (size_t)blockIdx.x * 256 + threadIdx.x;
    float4 v = X[i];
    size_t row = i / C4, c = i % C4;
    float h0 = to_tf32(v.x), h1 = to_tf32(v.y), h2 = to_tf32(v.z), h3 = to_tf32(v.w);
    Xs[row * 2 * C4 + c]      = make_float4(h0, h1, h2, h3);
    Xs[row * 2 * C4 + C4 + c] = make_float4(v.x - h0, v.y - h1, v.z - h2, v.w - h3);
}

// transpose X (R x C) -> XT (C x R); SPLIT: (C x 2R) hi|lo; else tf32-rounded
template<bool SPLIT>
__global__ void __launch_bounds__(256)
transpose_kernel(const float* __restrict__ X, float* __restrict__ XT, int R, int C)
{
    __shared__ float tile[32][33];
    int z = blockIdx.z;
    X  += (size_t)z * R * C;
    XT += (size_t)z * R * C * (SPLIT ? 2 : 1);
    int c0 = blockIdx.x * 32, r0 = blockIdx.y * 32;
    int tx = threadIdx.x & 31, ty = threadIdx.x >> 5;
#pragma unroll
    for (int k = 0; k < 4; ++k)
        tile[k * 8 + ty][tx] = X[(size_t)(r0 + k * 8 + ty) * C + c0 + tx];
    __syncthreads();
    int ldo = SPLIT ? 2 * R : R;
#pragma unroll
    for (int k = 0; k < 4; ++k) {
        int c = c0 + k * 8 + ty;
        float v = tile[tx][k * 8 + ty];
        if (SPLIT) {
            float h = to_tf32(v);
            XT[(size_t)c * ldo + r0 + tx]     = h;
            XT[(size_t)c * ldo + R + r0 + tx] = v - h;
        } else {
            XT[(size_t)c * ldo + r0 + tx] = to_tf32(v);
        }
    }
}

// ---------------- softmax stats + normalize --------------------------------
__global__ void __launch_bounds__(256)
rowstats_kernel(const float* __restrict__ E, float* __restrict__ rmax, float* __restrict__ rsum)
{
    int r = blockIdx.x * 8 + (threadIdx.x >> 5);
    int lane = threadIdx.x & 31;
    const float* row = E + (size_t)r * TT;
    float v[32];
    float m = -1e30f;
#pragma unroll
    for (int i = 0; i < 8; ++i) {
        float4 t = *reinterpret_cast<const float4*>(row + i * 128 + lane * 4);
        v[i*4+0]=t.x; v[i*4+1]=t.y; v[i*4+2]=t.z; v[i*4+3]=t.w;
        m = fmaxf(m, fmaxf(fmaxf(t.x, t.y), fmaxf(t.z, t.w)));
    }
#pragma unroll
    for (int o = 16; o > 0; o >>= 1) m = fmaxf(m, __shfl_xor_sync(0xffffffffu, m, o));
    float s = 0.f;
#pragma unroll
    for (int i = 0; i < 32; ++i) s += __expf(v[i] - m);
#pragma unroll
    for (int o = 16; o > 0; o >>= 1) s += __shfl_xor_sync(0xffffffffu, s, o);
    if (lane == 0) { rmax[r] = m; rsum[r] = s; }
}

__global__ void __launch_bounds__(256)
colstats_kernel(const float* __restrict__ E, float* __restrict__ cmax, float* __restrict__ csum)
{
    int b = blockIdx.x >> 2;
    int c = ((blockIdx.x & 3) << 8) + threadIdx.x;
    const float* base = E + (size_t)b * TT * TT + c;
    float m = -1e30f;
#pragma unroll 8
    for (int a = 0; a < TT; ++a) m = fmaxf(m, base[(size_t)a * TT]);
    float s = 0.f;
#pragma unroll 8
    for (int a = 0; a < TT; ++a) s += __expf(base[(size_t)a * TT] - m);
    cmax[b * TT + c] = m;
    csum[b * TT + c] = s;
}

__global__ void __launch_bounds__(256)
normexp_kernel(float* __restrict__ E, float* __restrict__ P2,
               const float* __restrict__ rmax, const float* __restrict__ rsum,
               const float* __restrict__ cmax, const float* __restrict__ csum)
{
    __shared__ float tile[32][33];
    int b = blockIdx.z;
    int a0 = blockIdx.y * 32, c0 = blockIdx.x * 32;
    int tx = threadIdx.x, ty = threadIdx.y;
    float* Eb = E  + (size_t)b * TT * TT;
    float* Pb = P2 + (size_t)b * TT * TT;
#pragma unroll
    for (int k = 0; k < 4; ++k) {
        int a = a0 + k * 8 + ty;
        float v = Eb[(size_t)a * TT + c0 + tx];
        tile[k * 8 + ty][tx] = v;
        int gr = b * TT + a;
        Eb[(size_t)a * TT + c0 + tx] = to_tf32(__expf(v - rmax[gr]) * __frcp_rn(rsum[gr]));
    }
    __syncthreads();
#pragma unroll
    for (int k = 0; k < 4; ++k) {
        int c = c0 + k * 8 + ty;
        float v = tile[tx][k * 8 + ty];
        int gc = b * TT + c;
        Pb[(size_t)c * TT + a0 + tx] = to_tf32(__expf(v - cmax[gc]) * __frcp_rn(csum[gc]));
    }
}

// ======================= launch ============================================
extern "C" void kernel_launch(void* const* d_in, const int* in_sizes, int n_in,
                              void* d_out, int out_size)
{
    const float* Ain = (const float*)d_in[0];
    const float* Bin = (const float*)d_in[1];
    const float* W1  = (const float*)d_in[2];
    const float* b1  = (const float*)d_in[3];
    const float* W2  = (const float*)d_in[4];
    const float* b2  = (const float*)d_in[5];
    float* outp = (float*)d_out;

    float *ABs, *W1Ts, *W2Ts, *Hs, *Fs, *E, *P2, *AT, *BT, *rm, *rs, *cm, *cs;
    cudaGetSymbolAddress((void**)&ABs,  g_ABs);
    cudaGetSymbolAddress((void**)&W1Ts, g_W1Ts);
    cudaGetSymbolAddress((void**)&W2Ts, g_W2Ts);
    cudaGetSymbolAddress((void**)&Hs,   g_Hs);
    cudaGetSymbolAddress((void**)&Fs,   g_Fs);
    cudaGetSymbolAddress((void**)&E,    g_E);
    cudaGetSymbolAddress((void**)&P2,   g_P2);
    cudaGetSymbolAddress((void**)&AT,   g_AT);
    cudaGetSymbolAddress((void**)&BT,   g_BT);
    cudaGetSymbolAddress((void**)&rm,   g_rmax);
    cudaGetSymbolAddress((void**)&rs,   g_rsum);
    cudaGetSymbolAddress((void**)&cm,   g_cmax);
    cudaGetSymbolAddress((void**)&cs,   g_csum);

    cudaFuncSetAttribute(gemm_mma<3, true,  true >, cudaFuncAttributeMaxDynamicSharedMemorySize, GEMM_SMEM);
    cudaFuncSetAttribute(gemm_mma<3, false, false>, cudaFuncAttributeMaxDynamicSharedMemorySize, GEMM_SMEM);
    cudaFuncSetAttribute(gemm_mma<1, false, false>, cudaFuncAttributeMaxDynamicSharedMemorySize, GEMM_SMEM);

    // ---- operand prep ----------------------------------------------------
    split_kernel<<<MROWS * (EMB/4) / 256, 256>>>((const float4*)Ain, (float4*)ABs, EMB/4);
    split_kernel<<<MROWS * (EMB/4) / 256, 256>>>((const float4*)Bin,
        (float4*)(ABs + (size_t)MROWS * 2 * EMB), EMB/4);
    transpose_kernel<true ><<<dim3(HID/32, EMB/32, 1), 256>>>(W1, W1Ts, EMB, HID);
    transpose_kernel<true ><<<dim3(HID/32, HID/32, 1), 256>>>(W2, W2Ts, HID, HID);
    transpose_kernel<false><<<dim3(EMB/32, TT/32, BSZ), 256>>>(Ain, AT, TT, EMB);
    transpose_kernel<false><<<dim3(EMB/32, TT/32, BSZ), 256>>>(Bin, BT, TT, EMB);

    // ---- MLP layer 1 (both A and B rows): Hs = split(relu(X @ W1 + b1)) --
    gemm_mma<3, true, true><<<dim3(HID/BN, 2*MROWS/BM, 1), 256, GEMM_SMEM>>>(
        ABs, 2*EMB, 0, W1Ts, 2*EMB, 0, b1, Hs, 2*HID, 0, HID, EMB,
        EMB, 0, 0, EMB);

    // ---- MLP layer 2: Fs = split(relu(Hs @ W2 + b2)) ----------------------
    gemm_mma<3, true, true><<<dim3(HID/BN, 2*MROWS/BM, 1), 256, GEMM_SMEM>>>(
        Hs, 2*HID, 0, W2Ts, 2*HID, 0, b2, Fs, 2*HID, 0, HID, HID,
        HID, 0, 0, HID);

    // ---- e[b] = f_A[b] @ f_B[b]^T -----------------------------------------
    gemm_mma<3, false, false><<<dim3(TT/BN, TT/BM, BSZ), 256, GEMM_SMEM>>>(
        Fs, 2*HID, (unsigned long long)TT * 2 * HID,
        Fs + (size_t)MROWS * 2 * HID, 2*HID, (unsigned long long)TT * 2 * HID,
        nullptr, E, TT, (unsigned long long)TT * TT, TT, HID,
        HID, 0, 0, HID);

    // ---- softmaxes ---------------------------------------------------------
    rowstats_kernel<<<MROWS/8, 256>>>(E, rm, rs);
    colstats_kernel<<<BSZ*4, 256>>>(E, cm, cs);
    normexp_kernel<<<dim3(TT/32, TT/32, BSZ), dim3(32, 8)>>>(E, P2, rm, rs, cm, cs);

    // ---- beta = P @ B ------------------------------------------------------
    gemm_mma<1, false, false><<<dim3(EMB/BN, TT/BM, BSZ), 256, GEMM_SMEM>>>(
        E, TT, (unsigned long long)TT * TT, BT, TT, (unsigned long long)EMB * TT,
        nullptr, outp, EMB, (unsigned long long)TT * EMB, EMB, TT, 0, 0, 0, 0);

    // ---- alpha = P2 @ A ----------------------------------------------------
    gemm_mma<1, false, false><<<dim3(EMB/BN, TT/BM, BSZ), 256, GEMM_SMEM>>>(
        P2, TT, (unsigned long long)TT * TT, AT, TT, (unsigned long long)EMB * TT,
        nullptr, outp + (size_t)BSZ * TT * EMB, EMB, (unsigned long long)TT * EMB,
        EMB, TT, 0, 0, 0, 0);
}

// round 4
// speedup vs baseline: 2.5693x; 1.8336x over previous
#include <cuda_runtime.h>
#include <cuda_fp16.h>
#include <cstdint>

// Problem shapes (fixed)
#define BSZ 16
#define TT  1024
#define EMB 768
#define HID 1024
#define MROWS (BSZ*TT)   // 16384 rows per tensor

// ======================= scratch (device globals) ==========================
__device__ __align__(128) __half g_ABh [(size_t)2 * MROWS * 2 * EMB];  // split inputs (32768 x 1536)
__device__ __align__(128) __half g_W1Th[(size_t)HID * 2 * EMB];        // W1^T split (1024 x 1536)
__device__ __align__(128) __half g_W2Th[(size_t)HID * 2 * HID];        // W2^T split (1024 x 2048)
__device__ __align__(128) __half g_Hh  [(size_t)2 * MROWS * 2 * HID];  // hidden split (32768 x 2048)
__device__ __align__(128) __half g_Fh  [(size_t)2 * MROWS * 2 * HID];  // MLP out split (32768 x 2048)
__device__ __align__(128) float  g_E   [(size_t)BSZ * TT * TT];        // e (fp32)
__device__ __align__(128) __half g_Ph  [(size_t)BSZ * TT * TT];        // row softmax (half)
__device__ __align__(128) __half g_P2h [(size_t)BSZ * TT * TT];        // col softmax, transposed (tb, ta)
__device__ __align__(128) __half g_ATh [(size_t)BSZ * EMB * TT];       // Ain^T per batch (768 x 1024)
__device__ __align__(128) __half g_BTh [(size_t)BSZ * EMB * TT];       // Bin^T per batch
__device__ float g_rmax[MROWS], g_rsum[MROWS];
__device__ float g_cmax[MROWS], g_csum[MROWS];

// ======================= helpers ===========================================
__device__ __forceinline__ uint32_t smem_u32(const void* p) {
    uint32_t a;
    asm("{ .reg .u64 t; cvta.to.shared.u64 t, %1; cvt.u32.u64 %0, t; }" : "=r"(a) : "l"(p));
    return a;
}
__device__ __forceinline__ void mma_f16(float* d, const uint32_t* a, const uint32_t* b) {
    asm volatile(
        "mma.sync.aligned.m16n8k16.row.col.f32.f16.f16.f32 "
        "{%0,%1,%2,%3}, {%4,%5,%6,%7}, {%8,%9}, {%0,%1,%2,%3};"
        : "+f"(d[0]), "+f"(d[1]), "+f"(d[2]), "+f"(d[3])
        : "r"(a[0]), "r"(a[1]), "r"(a[2]), "r"(a[3]), "r"(b[0]), "r"(b[1]));
}
__device__ __forceinline__ void split_h(float v, __half& hi, __half& lo) {
    hi = __float2half_rn(v);
    lo = __float2half_rn((v - __half2float(hi)) * 2048.0f);
}

// ======================= fp16 mma.sync GEMM ================================
// C(M,N) = [act]( sum_phases A_ph(M,K) * B_ph(N,K)^T [scaled] + bias )
// A, B K-major half. BM=256, BN=128, BK=64 halves. 8 warps = 4(m) x 2(n).
// 3-phase split: ph0 = A_lo*B_hi, ph1 = A_hi*B_lo (both w/ lo pre-scaled
// by 2048), then acc *= 2^-11, then ph2 = A_hi*B_hi.
#define BM 256
#define BN 128
#define BKH 64
#define SSTR 72                         // halves per smem row (conflict-free)
#define STG_BYTES ((BM + BN) * SSTR * 2)   // 55296
#define STG_A_BYTES (BM * SSTR * 2)        // 36864
#define GEMM_SMEM (3 * STG_BYTES)          // 165888

__device__ __forceinline__ void cp_stage_h(uint32_t stA, uint32_t stB,
    const __half* __restrict__ ga, int lda,
    const __half* __restrict__ gb, int ldb, int tid)
{
#pragma unroll
    for (int i = 0; i < 8; ++i) {                 // A: 256 rows x 8 x 16B
        int u = tid + i * 256;
        int r = u >> 3, c = u & 7;
        asm volatile("cp.async.cg.shared.global [%0], [%1], 16;"
            :: "r"(stA + (uint32_t)(r * (SSTR * 2) + c * 16)),
               "l"(ga + (size_t)r * lda + c * 8) : "memory");
    }
#pragma unroll
    for (int i = 0; i < 4; ++i) {                 // B: 128 rows x 8 x 16B
        int u = tid + i * 256;
        int r = u >> 3, c = u & 7;
        asm volatile("cp.async.cg.shared.global [%0], [%1], 16;"
            :: "r"(stB + (uint32_t)(r * (SSTR * 2) + c * 16)),
               "l"(gb + (size_t)r * ldb + c * 8) : "memory");
    }
}

template<int NPHASE, bool BIASRELU, bool HALFSPLITOUT>
__global__ void __launch_bounds__(256, 1)
gemm_h(const __half* __restrict__ Aop, int lda, unsigned long long sA,
       const __half* __restrict__ Bop, int ldb, unsigned long long sB,
       const float* __restrict__ bias,
       void* __restrict__ Cv, int ldc, unsigned long long sC,
       int N, int K)
{
    extern __shared__ __align__(128) __half smh[];
    uint32_t sbase = smem_u32(smh);
    const int tid  = threadIdx.x;
    const int lane = tid & 31;
    const int wid  = tid >> 5;
    const int wm   = wid >> 1;        // 0..3
    const int wn   = wid & 1;         // 0..1
    const int gr   = lane >> 2;       // 0..7
    const int tc   = lane & 3;        // 0..3
    const int m0 = blockIdx.y * BM;
    const int n0 = blockIdx.x * BN;

    const __half* Abase = Aop + (size_t)blockIdx.z * sA + (size_t)m0 * lda;
    const __half* Bbase = Bop + (size_t)blockIdx.z * sB + (size_t)n0 * ldb;

    const int KB = K / BKH;
    const int NT = NPHASE * KB;
    const int aoff0 = (NPHASE == 3) ? K : 0;     // phase0: A_lo
    const int boff1 = (NPHASE == 3) ? K : 0;     // phase1: B_lo

    float acc[4][8][4];
#pragma unroll
    for (int i = 0; i < 4; ++i)
#pragma unroll
        for (int j = 0; j < 8; ++j)
#pragma unroll
            for (int k = 0; k < 4; ++k) acc[i][j][k] = 0.f;

    // prologue: stages 0, 1 (both phase 0; KB >= 12 always here)
#pragma unroll 1
    for (int s = 0; s < 2; ++s) {
        uint32_t st = sbase + (uint32_t)s * STG_BYTES;
        cp_stage_h(st, st + STG_A_BYTES,
                   Abase + aoff0 + s * BKH, lda, Bbase + s * BKH, ldb, tid);
        asm volatile("cp.async.commit_group;" ::: "memory");
    }

#pragma unroll 1
    for (int kt = 0; kt < NT; ++kt) {
        asm volatile("cp.async.wait_group 1;" ::: "memory");
        __syncthreads();

        // prefetch kt+2
        {
            int nt = kt + 2;
            if (nt < NT) {
                int ph = nt / KB;
                int kk = nt - ph * KB;
                int oa = (ph == 0) ? aoff0 : 0;
                int ob = (ph == 1) ? boff1 : 0;
                uint32_t st = sbase + (uint32_t)(nt % 3) * STG_BYTES;
                cp_stage_h(st, st + STG_A_BYTES,
                           Abase + oa + kk * BKH, lda, Bbase + ob + kk * BKH, ldb, tid);
            }
            asm volatile("cp.async.commit_group;" ::: "memory");
        }

        // scale accumulated cross terms by 2^-11 at the phase-2 boundary
        if (NPHASE == 3 && kt == 2 * KB) {
#pragma unroll
            for (int i = 0; i < 4; ++i)
#pragma unroll
                for (int j = 0; j < 8; ++j)
#pragma unroll
                    for (int k = 0; k < 4; ++k) acc[i][j][k] *= 4.8828125e-4f;
        }

        const __half* sA = smh + (size_t)(kt % 3) * (STG_BYTES / 2);
        const __half* sB = sA + STG_A_BYTES / 2;
#pragma unroll
        for (int ks = 0; ks < 4; ++ks) {
            const int k0 = ks * 16;
            uint32_t af[4][4];
            uint32_t bf[8][2];
#pragma unroll
            for (int mi = 0; mi < 4; ++mi) {
                int r0 = wm * 64 + mi * 16 + gr;
                const __half* p0 = sA + r0 * SSTR + k0 + tc * 2;
                const __half* p1 = p0 + 8 * SSTR;
                af[mi][0] = *(const uint32_t*)p0;
                af[mi][1] = *(const uint32_t*)p1;
                af[mi][2] = *(const uint32_t*)(p0 + 8);
                af[mi][3] = *(const uint32_t*)(p1 + 8);
            }
#pragma unroll
            for (int ni = 0; ni < 8; ++ni) {
                int n = wn * 64 + ni * 8 + gr;
                const __half* p = sB + n * SSTR + k0 + tc * 2;
                bf[ni][0] = *(const uint32_t*)p;
                bf[ni][1] = *(const uint32_t*)(p + 8);
            }
#pragma unroll
            for (int mi = 0; mi < 4; ++mi)
#pragma unroll
                for (int ni = 0; ni < 8; ++ni)
                    mma_f16(acc[mi][ni], af[mi], bf[ni]);
        }
    }

    // ---- epilogue --------------------------------------------------------
#pragma unroll
    for (int ni = 0; ni < 8; ++ni) {
        int col = n0 + wn * 64 + ni * 8 + 2 * tc;
        float b0 = 0.f, b1 = 0.f;
        if (BIASRELU) { b0 = __ldg(bias + col); b1 = __ldg(bias + col + 1); }
#pragma unroll
        for (int mi = 0; mi < 4; ++mi) {
            int row0 = m0 + wm * 64 + mi * 16 + gr;
            float v00 = acc[mi][ni][0], v01 = acc[mi][ni][1];
            float v10 = acc[mi][ni][2], v11 = acc[mi][ni][3];
            if (BIASRELU) {
                v00 = fmaxf(v00 + b0, 0.f); v01 = fmaxf(v01 + b1, 0.f);
                v10 = fmaxf(v10 + b0, 0.f); v11 = fmaxf(v11 + b1, 0.f);
            }
            if (HALFSPLITOUT) {
                __half* C = (__half*)Cv + (size_t)blockIdx.z * sC;
                __half h00, l00, h01, l01, h10, l10, h11, l11;
                split_h(v00, h00, l00); split_h(v01, h01, l01);
                split_h(v10, h10, l10); split_h(v11, h11, l11);
                __half* p0 = C + (size_t)row0 * ldc + col;
                __half* p1 = C + (size_t)(row0 + 8) * ldc + col;
                *(__half2*)p0       = __halves2half2(h00, h01);
                *(__half2*)(p0 + N) = __halves2half2(l00, l01);
                *(__half2*)p1       = __halves2half2(h10, h11);
                *(__half2*)(p1 + N) = __halves2half2(l10, l11);
            } else {
                float* C = (float*)Cv + (size_t)blockIdx.z * sC;
                *(float2*)(C + (size_t)row0 * ldc + col)       = make_float2(v00, v01);
                *(float2*)(C + (size_t)(row0 + 8) * ldc + col) = make_float2(v10, v11);
            }
        }
    }
}

// ======================= fused prep kernel =================================
// Tasks: split A rows, split B rows, W1^T split, W2^T split, AT, BT.
#define NSPA ((MROWS * EMB) / 1024)            // 12288 (256 thr x float4)
#define NW1  ((EMB / 32) * (HID / 32))         // 768
#define NW2  ((HID / 32) * (HID / 32))         // 1024
#define NAT  (BSZ * (TT / 32) * (EMB / 32))    // 12288
#define PREP_BLOCKS (2 * NSPA + NW1 + NW2 + 2 * NAT)

__global__ void __launch_bounds__(256)
prep_kernel(const float* __restrict__ A, const float* __restrict__ Bn,
            const float* __restrict__ W1, const float* __restrict__ W2,
            __half* __restrict__ ABh, __half* __restrict__ W1Th,
            __half* __restrict__ W2Th, __half* __restrict__ ATh,
            __half* __restrict__ BTh)
{
    __shared__ float tile[32][33];
    int id = blockIdx.x;
    int tid = threadIdx.x;

    if (id < 2 * NSPA) {                       // -------- input splits
        bool isA = id < NSPA;
        const float4* src = (const float4*)(isA ? A : Bn);
        size_t rowoff = isA ? 0 : (size_t)MROWS;
        size_t i = (size_t)(id - (isA ? 0 : NSPA)) * 256 + tid;
        float4 v = src[i];
        size_t row = i / (EMB / 4), c = (i % (EMB / 4)) * 4;
        __half h0, l0, h1, l1, h2, l2, h3, l3;
        split_h(v.x, h0, l0); split_h(v.y, h1, l1);
        split_h(v.z, h2, l2); split_h(v.w, h3, l3);
        __half* dst = ABh + (row + rowoff) * (2 * EMB) + c;
        *(__half2*)dst           = __halves2half2(h0, h1);
        *(__half2*)(dst + 2)     = __halves2half2(h2, h3);
        *(__half2*)(dst + EMB)   = __halves2half2(l0, l1);
        *(__half2*)(dst + EMB+2) = __halves2half2(l2, l3);
        return;
    }
    id -= 2 * NSPA;

    int tx = tid & 31, ty = tid >> 5;
    if (id < NW1 + NW2) {                      // -------- weight transpose+split
        bool isW1 = id < NW1;
        int id2 = isW1 ? id : id - NW1;
        int R = isW1 ? EMB : HID;              // input rows (= output K)
        const float* W = isW1 ? W1 : W2;
        __half* WT = isW1 ? W1Th : W2Th;
        int rt = R / 32;
        int r0 = (id2 % rt) * 32, c0 = (id2 / rt) * 32;
#pragma unroll
        for (int k = 0; k < 4; ++k)
            tile[k * 8 + ty][tx] = W[(size_t)(r0 + k * 8 + ty) * HID + c0 + tx];
        __syncthreads();
#pragma unroll
        for (int k = 0; k < 4; ++k) {
            int c = c0 + k * 8 + ty;
            float v = tile[tx][k * 8 + ty];
            __half h, l; split_h(v, h, l);
            WT[(size_t)c * (2 * R) + r0 + tx]     = h;
            WT[(size_t)c * (2 * R) + R + r0 + tx] = l;
        }
        return;
    }
    id -= NW1 + NW2;

    {                                          // -------- AT / BT transposes
        bool isA = id < NAT;
        int id2 = isA ? id : id - NAT;
        const float* X = (isA ? A : Bn);
        __half* XT = (isA ? ATh : BTh);
        int batch = id2 / (NAT / BSZ);
        int t = id2 % (NAT / BSZ);              // 32 x 24 tiles over (1024 x 768)
        int r0 = (t % 32) * 32, c0 = (t / 32) * 32;
        X  += (size_t)batch * TT * EMB;
        XT += (size_t)batch * EMB * TT;
#pragma unroll
        for (int k = 0; k < 4; ++k)
            tile[k * 8 + ty][tx] = X[(size_t)(r0 + k * 8 + ty) * EMB + c0 + tx];
        __syncthreads();
#pragma unroll
        for (int k = 0; k < 4; ++k) {
            int c = c0 + k * 8 + ty;
            XT[(size_t)c * TT + r0 + tx] = __float2half_rn(tile[tx][k * 8 + ty]);
        }
    }
}

// ---------------- softmax stats + normalize --------------------------------
__global__ void __launch_bounds__(256)
rowstats_kernel(const float* __restrict__ E, float* __restrict__ rmax, float* __restrict__ rsum)
{
    int r = blockIdx.x * 8 + (threadIdx.x >> 5);
    int lane = threadIdx.x & 31;
    const float* row = E + (size_t)r * TT;
    float v[32];
    float m = -1e30f;
#pragma unroll
    for (int i = 0; i < 8; ++i) {
        float4 t = *reinterpret_cast<const float4*>(row + i * 128 + lane * 4);
        v[i*4+0]=t.x; v[i*4+1]=t.y; v[i*4+2]=t.z; v[i*4+3]=t.w;
        m = fmaxf(m, fmaxf(fmaxf(t.x, t.y), fmaxf(t.z, t.w)));
    }
#pragma unroll
    for (int o = 16; o > 0; o >>= 1) m = fmaxf(m, __shfl_xor_sync(0xffffffffu, m, o));
    float s = 0.f;
#pragma unroll
    for (int i = 0; i < 32; ++i) s += __expf(v[i] - m);
#pragma unroll
    for (int o = 16; o > 0; o >>= 1) s += __shfl_xor_sync(0xffffffffu, s, o);
    if (lane == 0) { rmax[r] = m; rsum[r] = s; }
}

__global__ void __launch_bounds__(256)
colstats_kernel(const float* __restrict__ E, float* __restrict__ cmax, float* __restrict__ csum)
{
    int b = blockIdx.x >> 2;
    int c = ((blockIdx.x & 3) << 8) + threadIdx.x;
    const float* base = E + (size_t)b * TT * TT + c;
    float m = -1e30f;
#pragma unroll 8
    for (int a = 0; a < TT; ++a) m = fmaxf(m, base[(size_t)a * TT]);
    float s = 0.f;
#pragma unroll 8
    for (int a = 0; a < TT; ++a) s += __expf(base[(size_t)a * TT] - m);
    cmax[b * TT + c] = m;
    csum[b * TT + c] = s;
}

__global__ void __launch_bounds__(256)
normexp_kernel(const float* __restrict__ E, __half* __restrict__ P, __half* __restrict__ P2,
               const float* __restrict__ rmax, const float* __restrict__ rsum,
               const float* __restrict__ cmax, const float* __restrict__ csum)
{
    __shared__ float tile[32][33];
    int b = blockIdx.z;
    int a0 = blockIdx.y * 32, c0 = blockIdx.x * 32;
    int tx = threadIdx.x, ty = threadIdx.y;
    const float* Eb = E + (size_t)b * TT * TT;
    __half* Pb  = P  + (size_t)b * TT * TT;
    __half* P2b = P2 + (size_t)b * TT * TT;
#pragma unroll
    for (int k = 0; k < 4; ++k) {
        int a = a0 + k * 8 + ty;
        float v = Eb[(size_t)a * TT + c0 + tx];
        tile[k * 8 + ty][tx] = v;
        int gr = b * TT + a;
        Pb[(size_t)a * TT + c0 + tx] =
            __float2half_rn(__expf(v - rmax[gr]) * __frcp_rn(rsum[gr]));
    }
    __syncthreads();
#pragma unroll
    for (int k = 0; k < 4; ++k) {
        int c = c0 + k * 8 + ty;
        float v = tile[tx][k * 8 + ty];
        int gc = b * TT + c;
        P2b[(size_t)c * TT + a0 + tx] =
            __float2half_rn(__expf(v - cmax[gc]) * __frcp_rn(csum[gc]));
    }
}

// ======================= launch ============================================
extern "C" void kernel_launch(void* const* d_in, const int* in_sizes, int n_in,
                              void* d_out, int out_size)
{
    const float* Ain = (const float*)d_in[0];
    const float* Bin = (const float*)d_in[1];
    const float* W1  = (const float*)d_in[2];
    const float* b1  = (const float*)d_in[3];
    const float* W2  = (const float*)d_in[4];
    const float* b2  = (const float*)d_in[5];
    float* outp = (float*)d_out;

    __half *ABh, *W1Th, *W2Th, *Hh, *Fh, *Ph, *P2h, *ATh, *BTh;
    float *E, *rm, *rs, *cm, *cs;
    cudaGetSymbolAddress((void**)&ABh,  g_ABh);
    cudaGetSymbolAddress((void**)&W1Th, g_W1Th);
    cudaGetSymbolAddress((void**)&W2Th, g_W2Th);
    cudaGetSymbolAddress((void**)&Hh,   g_Hh);
    cudaGetSymbolAddress((void**)&Fh,   g_Fh);
    cudaGetSymbolAddress((void**)&E,    g_E);
    cudaGetSymbolAddress((void**)&Ph,   g_Ph);
    cudaGetSymbolAddress((void**)&P2h,  g_P2h);
    cudaGetSymbolAddress((void**)&ATh,  g_ATh);
    cudaGetSymbolAddress((void**)&BTh,  g_BTh);
    cudaGetSymbolAddress((void**)&rm,   g_rmax);
    cudaGetSymbolAddress((void**)&rs,   g_rsum);
    cudaGetSymbolAddress((void**)&cm,   g_cmax);
    cudaGetSymbolAddress((void**)&cs,   g_csum);

    cudaFuncSetAttribute(gemm_h<3, true,  true >, cudaFuncAttributeMaxDynamicSharedMemorySize, GEMM_SMEM);
    cudaFuncSetAttribute(gemm_h<3, false, false>, cudaFuncAttributeMaxDynamicSharedMemorySize, GEMM_SMEM);
    cudaFuncSetAttribute(gemm_h<1, false, false>, cudaFuncAttributeMaxDynamicSharedMemorySize, GEMM_SMEM);

    // 1) operand prep (single fused kernel)
    prep_kernel<<<PREP_BLOCKS, 256>>>(Ain, Bin, W1, W2, ABh, W1Th, W2Th, ATh, BTh);

    // 2) MLP layer 1 (A and B rows together): Hh = split(relu(X @ W1 + b1))
    gemm_h<3, true, true><<<dim3(HID/BN, 2*MROWS/BM, 1), 256, GEMM_SMEM>>>(
        ABh, 2*EMB, 0, W1Th, 2*EMB, 0, b1, Hh, 2*HID, 0, HID, EMB);

    // 3) MLP layer 2: Fh = split(relu(Hh @ W2 + b2))
    gemm_h<3, true, true><<<dim3(HID/BN, 2*MROWS/BM, 1), 256, GEMM_SMEM>>>(
        Hh, 2*HID, 0, W2Th, 2*HID, 0, b2, Fh, 2*HID, 0, HID, HID);

    // 4) e[b] = f_A[b] @ f_B[b]^T (fp32 out)
    gemm_h<3, false, false><<<dim3(TT/BN, TT/BM, BSZ), 256, GEMM_SMEM>>>(
        Fh, 2*HID, (unsigned long long)TT * 2 * HID,
        Fh + (size_t)MROWS * 2 * HID, 2*HID, (unsigned long long)TT * 2 * HID,
        nullptr, E, TT, (unsigned long long)TT * TT, TT, HID);

    // 5-7) softmaxes
    rowstats_kernel<<<MROWS/8, 256>>>(E, rm, rs);
    colstats_kernel<<<BSZ*4, 256>>>(E, cm, cs);
    normexp_kernel<<<dim3(TT/32, TT/32, BSZ), dim3(32, 8)>>>(E, Ph, P2h, rm, rs, cm, cs);

    // 8) beta = P @ B
    gemm_h<1, false, false><<<dim3(EMB/BN, TT/BM, BSZ), 256, GEMM_SMEM>>>(
        Ph, TT, (unsigned long long)TT * TT, BTh, TT, (unsigned long long)EMB * TT,
        nullptr, outp, EMB, (unsigned long long)TT * EMB, EMB, TT);

    // 9) alpha = P2 @ A
    gemm_h<1, false, false><<<dim3(EMB/BN, TT/BM, BSZ), 256, GEMM_SMEM>>>(
        P2h, TT, (unsigned long long)TT * TT, ATh, TT, (unsigned long long)EMB * TT,
        nullptr, outp + (size_t)BSZ * TT * EMB, EMB, (unsigned long long)TT * EMB, EMB, TT);
}

// round 5
// speedup vs baseline: 2.6774x; 1.0421x over previous
#include <cuda_runtime.h>
#include <cuda_fp16.h>
#include <cstdint>

// Problem shapes (fixed)
#define BSZ 16
#define TT  1024
#define EMB 768
#define HID 1024
#define MROWS (BSZ*TT)   // 16384 rows per tensor

// ======================= scratch (device globals) ==========================
__device__ __align__(128) __half g_ABh [(size_t)2 * MROWS * 2 * EMB];  // split inputs (32768 x 1536)
__device__ __align__(128) __half g_W1Th[(size_t)HID * 2 * EMB];        // W1^T split (1024 x 1536)
__device__ __align__(128) __half g_W2Th[(size_t)HID * 2 * HID];        // W2^T split (1024 x 2048)
__device__ __align__(128) __half g_Hh  [(size_t)2 * MROWS * 2 * HID];  // hidden split (32768 x 2048)
__device__ __align__(128) __half g_Fh  [(size_t)2 * MROWS * 2 * HID];  // MLP out split (32768 x 2048)
__device__ __align__(128) float  g_E   [(size_t)BSZ * TT * TT];        // e (fp32)
__device__ __align__(128) __half g_Ph  [(size_t)BSZ * TT * TT];        // row softmax (half)
__device__ __align__(128) __half g_P2h [(size_t)BSZ * TT * TT];        // col softmax, transposed (tb, ta)
__device__ __align__(128) __half g_ATh [(size_t)BSZ * EMB * TT];       // Ain^T per batch (768 x 1024)
__device__ __align__(128) __half g_BTh [(size_t)BSZ * EMB * TT];       // Bin^T per batch
__device__ float g_rmax[MROWS], g_rsum[MROWS];
__device__ float g_cmax[MROWS], g_csum[MROWS];

// ======================= helpers ===========================================
__device__ __forceinline__ uint32_t smem_u32(const void* p) {
    uint32_t a;
    asm("{ .reg .u64 t; cvta.to.shared.u64 t, %1; cvt.u32.u64 %0, t; }" : "=r"(a) : "l"(p));
    return a;
}
__device__ __forceinline__ void mma_f16(float* d, const uint32_t* a, const uint32_t* b) {
    asm volatile(
        "mma.sync.aligned.m16n8k16.row.col.f32.f16.f16.f32 "
        "{%0,%1,%2,%3}, {%4,%5,%6,%7}, {%8,%9}, {%0,%1,%2,%3};"
        : "+f"(d[0]), "+f"(d[1]), "+f"(d[2]), "+f"(d[3])
        : "r"(a[0]), "r"(a[1]), "r"(a[2]), "r"(a[3]), "r"(b[0]), "r"(b[1]));
}
__device__ __forceinline__ void ldsm_x4(uint32_t& r0, uint32_t& r1,
                                        uint32_t& r2, uint32_t& r3, uint32_t addr) {
    asm volatile("ldmatrix.sync.aligned.m8n8.x4.shared.b16 {%0,%1,%2,%3}, [%4];"
        : "=r"(r0), "=r"(r1), "=r"(r2), "=r"(r3) : "r"(addr));
}
__device__ __forceinline__ void split_h(float v, __half& hi, __half& lo) {
    hi = __float2half_rn(v);
    lo = __float2half_rn((v - __half2float(hi)) * 2048.0f);
}

// ======================= fp16 mma.sync GEMM ================================
// C(M,N) = [act]( sum_phases A_ph(M,K) * B_ph(N,K)^T [scaled] + bias )
// A, B K-major half. BM=256, BN=128, BK=64 halves. 8 warps = 4(m) x 2(n).
// 3-phase split: ph0 = A_lo*B_hi, ph1 = A_hi*B_lo (lo pre-scaled by 2048),
// then acc *= 2^-11, then ph2 = A_hi*B_hi.
#define BM 256
#define BN 128
#define BKH 64
#define SSTR 72                            // halves per smem row (LDSM conflict-free)
#define STG_BYTES ((BM + BN) * SSTR * 2)   // 55296
#define STG_A_BYTES (BM * SSTR * 2)        // 36864
#define GEMM_SMEM (3 * STG_BYTES)          // 165888

__device__ __forceinline__ void cp_stage_h(uint32_t stA, uint32_t stB,
    const __half* __restrict__ ga, int lda,
    const __half* __restrict__ gb, int ldb, int tid)
{
#pragma unroll
    for (int i = 0; i < 8; ++i) {                 // A: 256 rows x 8 x 16B
        int u = tid + i * 256;
        int r = u >> 3, c = u & 7;
        asm volatile("cp.async.cg.shared.global [%0], [%1], 16;"
            :: "r"(stA + (uint32_t)(r * (SSTR * 2) + c * 16)),
               "l"(ga + (size_t)r * lda + c * 8) : "memory");
    }
#pragma unroll
    for (int i = 0; i < 4; ++i) {                 // B: 128 rows x 8 x 16B
        int u = tid + i * 256;
        int r = u >> 3, c = u & 7;
        asm volatile("cp.async.cg.shared.global [%0], [%1], 16;"
            :: "r"(stB + (uint32_t)(r * (SSTR * 2) + c * 16)),
               "l"(gb + (size_t)r * ldb + c * 8) : "memory");
    }
}

template<int NPHASE, bool BIASRELU, bool HALFSPLITOUT>
__global__ void __launch_bounds__(256, 1)
gemm_h(const __half* __restrict__ Aop, int lda, unsigned long long sA,
       const __half* __restrict__ Bop, int ldb, unsigned long long sB,
       const float* __restrict__ bias,
       void* __restrict__ Cv, int ldc, unsigned long long sC,
       int N, int K)
{
    extern __shared__ __align__(128) __half smh[];
    uint32_t sbase = smem_u32(smh);
    const int tid  = threadIdx.x;
    const int lane = tid & 31;
    const int wid  = tid >> 5;
    const int wm   = wid >> 1;        // 0..3
    const int wn   = wid & 1;         // 0..1
    const int gr   = lane >> 2;       // 0..7 (mma fragment row group)
    const int tc   = lane & 3;        // 0..3
    const int m0 = blockIdx.y * BM;
    const int n0 = blockIdx.x * BN;

    const __half* Abase = Aop + (size_t)blockIdx.z * sA + (size_t)m0 * lda;
    const __half* Bbase = Bop + (size_t)blockIdx.z * sB + (size_t)n0 * ldb;

    const int KB = K / BKH;
    const int NT = NPHASE * KB;
    const int aoff0 = (NPHASE == 3) ? K : 0;     // phase0: A_lo
    const int boff1 = (NPHASE == 3) ? K : 0;     // phase1: B_lo

    // ---- per-lane LDSM base offsets (bytes, relative to stage A/B bases) --
    const int lg = lane >> 3;          // ldmatrix lane group 0..3
    const int r8 = lane & 7;
    uint32_t aOff[4], bOff[4];
#pragma unroll
    for (int mi = 0; mi < 4; ++mi)     // A: m8 blocks via (lg&1), k+8 via (lg>>1)
        aOff[mi] = (uint32_t)(((wm * 64 + mi * 16 + (lg & 1) * 8 + r8) * SSTR
                               + (lg >> 1) * 8) * 2);
#pragma unroll
    for (int pn = 0; pn < 4; ++pn)     // B: k+8 via (lg&1), n+8 via (lg>>1)
        bOff[pn] = (uint32_t)(((wn * 64 + pn * 16 + (lg >> 1) * 8 + r8) * SSTR
                               + (lg & 1) * 8) * 2);

    float acc[4][8][4];
#pragma unroll
    for (int i = 0; i < 4; ++i)
#pragma unroll
        for (int j = 0; j < 8; ++j)
#pragma unroll
            for (int k = 0; k < 4; ++k) acc[i][j][k] = 0.f;

    // prologue: stages 0, 1 (both phase 0; KB >= 12 always here)
#pragma unroll 1
    for (int s = 0; s < 2; ++s) {
        uint32_t st = sbase + (uint32_t)s * STG_BYTES;
        cp_stage_h(st, st + STG_A_BYTES,
                   Abase + aoff0 + s * BKH, lda, Bbase + s * BKH, ldb, tid);
        asm volatile("cp.async.commit_group;" ::: "memory");
    }

#pragma unroll 1
    for (int kt = 0; kt < NT; ++kt) {
        asm volatile("cp.async.wait_group 1;" ::: "memory");
        __syncthreads();

        // prefetch kt+2
        {
            int nt = kt + 2;
            if (nt < NT) {
                int ph = nt / KB;
                int kk = nt - ph * KB;
                int oa = (ph == 0) ? aoff0 : 0;
                int ob = (ph == 1) ? boff1 : 0;
                uint32_t st = sbase + (uint32_t)(nt % 3) * STG_BYTES;
                cp_stage_h(st, st + STG_A_BYTES,
                           Abase + oa + kk * BKH, lda, Bbase + ob + kk * BKH, ldb, tid);
            }
            asm volatile("cp.async.commit_group;" ::: "memory");
        }

        // scale accumulated cross terms by 2^-11 at the phase-2 boundary
        if (NPHASE == 3 && kt == 2 * KB) {
#pragma unroll
            for (int i = 0; i < 4; ++i)
#pragma unroll
                for (int j = 0; j < 8; ++j)
#pragma unroll
                    for (int k = 0; k < 4; ++k) acc[i][j][k] *= 4.8828125e-4f;
        }

        uint32_t stA = sbase + (uint32_t)(kt % 3) * STG_BYTES;
        uint32_t stB = stA + STG_A_BYTES;
#pragma unroll
        for (int ks = 0; ks < 4; ++ks) {
            const uint32_t kb = (uint32_t)(ks * 32);   // 16 halves per ks
            uint32_t af[4][4];
            uint32_t bf[8][2];
#pragma unroll
            for (int mi = 0; mi < 4; ++mi)
                ldsm_x4(af[mi][0], af[mi][1], af[mi][2], af[mi][3],
                        stA + aOff[mi] + kb);
#pragma unroll
            for (int pn = 0; pn < 4; ++pn) {
                uint32_t t0, t1, t2, t3;
                ldsm_x4(t0, t1, t2, t3, stB + bOff[pn] + kb);
                bf[2 * pn][0] = t0;  bf[2 * pn][1] = t1;
                bf[2 * pn + 1][0] = t2;  bf[2 * pn + 1][1] = t3;
            }
#pragma unroll
            for (int mi = 0; mi < 4; ++mi)
#pragma unroll
                for (int ni = 0; ni < 8; ++ni)
                    mma_f16(acc[mi][ni], af[mi], bf[ni]);
        }
    }

    // ---- epilogue --------------------------------------------------------
#pragma unroll
    for (int ni = 0; ni < 8; ++ni) {
        int col = n0 + wn * 64 + ni * 8 + 2 * tc;
        float b0 = 0.f, b1 = 0.f;
        if (BIASRELU) { b0 = __ldg(bias + col); b1 = __ldg(bias + col + 1); }
#pragma unroll
        for (int mi = 0; mi < 4; ++mi) {
            int row0 = m0 + wm * 64 + mi * 16 + gr;
            float v00 = acc[mi][ni][0], v01 = acc[mi][ni][1];
            float v10 = acc[mi][ni][2], v11 = acc[mi][ni][3];
            if (BIASRELU) {
                v00 = fmaxf(v00 + b0, 0.f); v01 = fmaxf(v01 + b1, 0.f);
                v10 = fmaxf(v10 + b0, 0.f); v11 = fmaxf(v11 + b1, 0.f);
            }
            if (HALFSPLITOUT) {
                __half* C = (__half*)Cv + (size_t)blockIdx.z * sC;
                __half h00, l00, h01, l01, h10, l10, h11, l11;
                split_h(v00, h00, l00); split_h(v01, h01, l01);
                split_h(v10, h10, l10); split_h(v11, h11, l11);
                __half* p0 = C + (size_t)row0 * ldc + col;
                __half* p1 = C + (size_t)(row0 + 8) * ldc + col;
                *(__half2*)p0       = __halves2half2(h00, h01);
                *(__half2*)(p0 + N) = __halves2half2(l00, l01);
                *(__half2*)p1       = __halves2half2(h10, h11);
                *(__half2*)(p1 + N) = __halves2half2(l10, l11);
            } else {
                float* C = (float*)Cv + (size_t)blockIdx.z * sC;
                *(float2*)(C + (size_t)row0 * ldc + col)       = make_float2(v00, v01);
                *(float2*)(C + (size_t)(row0 + 8) * ldc + col) = make_float2(v10, v11);
            }
        }
    }
}

// ======================= fused prep kernel =================================
#define NSPA ((MROWS * EMB) / 1024)            // 12288 (256 thr x float4)
#define NW1  ((EMB / 32) * (HID / 32))         // 768
#define NW2  ((HID / 32) * (HID / 32))         // 1024
#define NAT  (BSZ * (TT / 32) * (EMB / 32))    // 12288
#define PREP_BLOCKS (2 * NSPA + NW1 + NW2 + 2 * NAT)

__global__ void __launch_bounds__(256)
prep_kernel(const float* __restrict__ A, const float* __restrict__ Bn,
            const float* __restrict__ W1, const float* __restrict__ W2,
            __half* __restrict__ ABh, __half* __restrict__ W1Th,
            __half* __restrict__ W2Th, __half* __restrict__ ATh,
            __half* __restrict__ BTh)
{
    __shared__ float tile[32][33];
    int id = blockIdx.x;
    int tid = threadIdx.x;

    if (id < 2 * NSPA) {                       // -------- input splits
        bool isA = id < NSPA;
        const float4* src = (const float4*)(isA ? A : Bn);
        size_t rowoff = isA ? 0 : (size_t)MROWS;
        size_t i = (size_t)(id - (isA ? 0 : NSPA)) * 256 + tid;
        float4 v = src[i];
        size_t row = i / (EMB / 4), c = (i % (EMB / 4)) * 4;
        __half h0, l0, h1, l1, h2, l2, h3, l3;
        split_h(v.x, h0, l0); split_h(v.y, h1, l1);
        split_h(v.z, h2, l2); split_h(v.w, h3, l3);
        __half* dst = ABh + (row + rowoff) * (2 * EMB) + c;
        *(__half2*)dst           = __halves2half2(h0, h1);
        *(__half2*)(dst + 2)     = __halves2half2(h2, h3);
        *(__half2*)(dst + EMB)   = __halves2half2(l0, l1);
        *(__half2*)(dst + EMB+2) = __halves2half2(l2, l3);
        return;
    }
    id -= 2 * NSPA;

    int tx = tid & 31, ty = tid >> 5;
    if (id < NW1 + NW2) {                      // -------- weight transpose+split
        bool isW1 = id < NW1;
        int id2 = isW1 ? id : id - NW1;
        int R = isW1 ? EMB : HID;
        const float* W = isW1 ? W1 : W2;
        __half* WT = isW1 ? W1Th : W2Th;
        int rt = R / 32;
        int r0 = (id2 % rt) * 32, c0 = (id2 / rt) * 32;
#pragma unroll
        for (int k = 0; k < 4; ++k)
            tile[k * 8 + ty][tx] = W[(size_t)(r0 + k * 8 + ty) * HID + c0 + tx];
        __syncthreads();
#pragma unroll
        for (int k = 0; k < 4; ++k) {
            int c = c0 + k * 8 + ty;
            float v = tile[tx][k * 8 + ty];
            __half h, l; split_h(v, h, l);
            WT[(size_t)c * (2 * R) + r0 + tx]     = h;
            WT[(size_t)c * (2 * R) + R + r0 + tx] = l;
        }
        return;
    }
    id -= NW1 + NW2;

    {                                          // -------- AT / BT transposes
        bool isA = id < NAT;
        int id2 = isA ? id : id - NAT;
        const float* X = (isA ? A : Bn);
        __half* XT = (isA ? ATh : BTh);
        int batch = id2 / (NAT / BSZ);
        int t = id2 % (NAT / BSZ);
        int r0 = (t % 32) * 32, c0 = (t / 32) * 32;
        X  += (size_t)batch * TT * EMB;
        XT += (size_t)batch * EMB * TT;
#pragma unroll
        for (int k = 0; k < 4; ++k)
            tile[k * 8 + ty][tx] = X[(size_t)(r0 + k * 8 + ty) * EMB + c0 + tx];
        __syncthreads();
#pragma unroll
        for (int k = 0; k < 4; ++k) {
            int c = c0 + k * 8 + ty;
            XT[(size_t)c * TT + r0 + tx] = __float2half_rn(tile[tx][k * 8 + ty]);
        }
    }
}

// ---------------- softmax stats + normalize --------------------------------
__global__ void __launch_bounds__(256)
rowstats_kernel(const float* __restrict__ E, float* __restrict__ rmax, float* __restrict__ rsum)
{
    int r = blockIdx.x * 8 + (threadIdx.x >> 5);
    int lane = threadIdx.x & 31;
    const float* row = E + (size_t)r * TT;
    float v[32];
    float m = -1e30f;
#pragma unroll
    for (int i = 0; i < 8; ++i) {
        float4 t = *reinterpret_cast<const float4*>(row + i * 128 + lane * 4);
        v[i*4+0]=t.x; v[i*4+1]=t.y; v[i*4+2]=t.z; v[i*4+3]=t.w;
        m = fmaxf(m, fmaxf(fmaxf(t.x, t.y), fmaxf(t.z, t.w)));
    }
#pragma unroll
    for (int o = 16; o > 0; o >>= 1) m = fmaxf(m, __shfl_xor_sync(0xffffffffu, m, o));
    float s = 0.f;
#pragma unroll
    for (int i = 0; i < 32; ++i) s += __expf(v[i] - m);
#pragma unroll
    for (int o = 16; o > 0; o >>= 1) s += __shfl_xor_sync(0xffffffffu, s, o);
    if (lane == 0) { rmax[r] = m; rsum[r] = s; }
}

__global__ void __launch_bounds__(256)
colstats_kernel(const float* __restrict__ E, float* __restrict__ cmax, float* __restrict__ csum)
{
    int b = blockIdx.x >> 2;
    int c = ((blockIdx.x & 3) << 8) + threadIdx.x;
    const float* base = E + (size_t)b * TT * TT + c;
    float m = -1e30f;
#pragma unroll 8
    for (int a = 0; a < TT; ++a) m = fmaxf(m, base[(size_t)a * TT]);
    float s = 0.f;
#pragma unroll 8
    for (int a = 0; a < TT; ++a) s += __expf(base[(size_t)a * TT] - m);
    cmax[b * TT + c] = m;
    csum[b * TT + c] = s;
}

__global__ void __launch_bounds__(256)
normexp_kernel(const float* __restrict__ E, __half* __restrict__ P, __half* __restrict__ P2,
               const float* __restrict__ rmax, const float* __restrict__ rsum,
               const float* __restrict__ cmax, const float* __restrict__ csum)
{
    __shared__ float tile[32][33];
    int b = blockIdx.z;
    int a0 = blockIdx.y * 32, c0 = blockIdx.x * 32;
    int tx = threadIdx.x, ty = threadIdx.y;
    const float* Eb = E + (size_t)b * TT * TT;
    __half* Pb  = P  + (size_t)b * TT * TT;
    __half* P2b = P2 + (size_t)b * TT * TT;
#pragma unroll
    for (int k = 0; k < 4; ++k) {
        int a = a0 + k * 8 + ty;
        float v = Eb[(size_t)a * TT + c0 + tx];
        tile[k * 8 + ty][tx] = v;
        int gr = b * TT + a;
        Pb[(size_t)a * TT + c0 + tx] =
            __float2half_rn(__expf(v - rmax[gr]) * __frcp_rn(rsum[gr]));
    }
    __syncthreads();
#pragma unroll
    for (int k = 0; k < 4; ++k) {
        int c = c0 + k * 8 + ty;
        float v = tile[tx][k * 8 + ty];
        int gc = b * TT + c;
        P2b[(size_t)c * TT + a0 + tx] =
            __float2half_rn(__expf(v - cmax[gc]) * __frcp_rn(csum[gc]));
    }
}

// ======================= launch ============================================
extern "C" void kernel_launch(void* const* d_in, const int* in_sizes, int n_in,
                              void* d_out, int out_size)
{
    const float* Ain = (const float*)d_in[0];
    const float* Bin = (const float*)d_in[1];
    const float* W1  = (const float*)d_in[2];
    const float* b1  = (const float*)d_in[3];
    const float* W2  = (const float*)d_in[4];
    const float* b2  = (const float*)d_in[5];
    float* outp = (float*)d_out;

    __half *ABh, *W1Th, *W2Th, *Hh, *Fh, *Ph, *P2h, *ATh, *BTh;
    float *E, *rm, *rs, *cm, *cs;
    cudaGetSymbolAddress((void**)&ABh,  g_ABh);
    cudaGetSymbolAddress((void**)&W1Th, g_W1Th);
    cudaGetSymbolAddress((void**)&W2Th, g_W2Th);
    cudaGetSymbolAddress((void**)&Hh,   g_Hh);
    cudaGetSymbolAddress((void**)&Fh,   g_Fh);
    cudaGetSymbolAddress((void**)&E,    g_E);
    cudaGetSymbolAddress((void**)&Ph,   g_Ph);
    cudaGetSymbolAddress((void**)&P2h,  g_P2h);
    cudaGetSymbolAddress((void**)&ATh,  g_ATh);
    cudaGetSymbolAddress((void**)&BTh,  g_BTh);
    cudaGetSymbolAddress((void**)&rm,   g_rmax);
    cudaGetSymbolAddress((void**)&rs,   g_rsum);
    cudaGetSymbolAddress((void**)&cm,   g_cmax);
    cudaGetSymbolAddress((void**)&cs,   g_csum);

    cudaFuncSetAttribute(gemm_h<3, true,  true >, cudaFuncAttributeMaxDynamicSharedMemorySize, GEMM_SMEM);
    cudaFuncSetAttribute(gemm_h<3, false, false>, cudaFuncAttributeMaxDynamicSharedMemorySize, GEMM_SMEM);
    cudaFuncSetAttribute(gemm_h<1, false, false>, cudaFuncAttributeMaxDynamicSharedMemorySize, GEMM_SMEM);

    // 1) operand prep (single fused kernel)
    prep_kernel<<<PREP_BLOCKS, 256>>>(Ain, Bin, W1, W2, ABh, W1Th, W2Th, ATh, BTh);

    // 2) MLP layer 1 (A and B rows together): Hh = split(relu(X @ W1 + b1))
    gemm_h<3, true, true><<<dim3(HID/BN, 2*MROWS/BM, 1), 256, GEMM_SMEM>>>(
        ABh, 2*EMB, 0, W1Th, 2*EMB, 0, b1, Hh, 2*HID, 0, HID, EMB);

    // 3) MLP layer 2: Fh = split(relu(Hh @ W2 + b2))
    gemm_h<3, true, true><<<dim3(HID/BN, 2*MROWS/BM, 1), 256, GEMM_SMEM>>>(
        Hh, 2*HID, 0, W2Th, 2*HID, 0, b2, Fh, 2*HID, 0, HID, HID);

    // 4) e[b] = f_A[b] @ f_B[b]^T (fp32 out)
    gemm_h<3, false, false><<<dim3(TT/BN, TT/BM, BSZ), 256, GEMM_SMEM>>>(
        Fh, 2*HID, (unsigned long long)TT * 2 * HID,
        Fh + (size_t)MROWS * 2 * HID, 2*HID, (unsigned long long)TT * 2 * HID,
        nullptr, E, TT, (unsigned long long)TT * TT, TT, HID);

    // 5-7) softmaxes
    rowstats_kernel<<<MROWS/8, 256>>>(E, rm, rs);
    colstats_kernel<<<BSZ*4, 256>>>(E, cm, cs);
    normexp_kernel<<<dim3(TT/32, TT/32, BSZ), dim3(32, 8)>>>(E, Ph, P2h, rm, rs, cm, cs);

    // 8) beta = P @ B
    gemm_h<1, false, false><<<dim3(EMB/BN, TT/BM, BSZ), 256, GEMM_SMEM>>>(
        Ph, TT, (unsigned long long)TT * TT, BTh, TT, (unsigned long long)EMB * TT,
        nullptr, outp, EMB, (unsigned long long)TT * EMB, EMB, TT);

    // 9) alpha = P2 @ A
    gemm_h<1, false, false><<<dim3(EMB/BN, TT/BM, BSZ), 256, GEMM_SMEM>>>(
        P2h, TT, (unsigned long long)TT * TT, ATh, TT, (unsigned long long)EMB * TT,
        nullptr, outp + (size_t)BSZ * TT * EMB, EMB, (unsigned long long)TT * EMB, EMB, TT);
}